// round 13
// baseline (speedup 1.0000x reference)
#include <cuda_runtime.h>
#include <cuda_fp16.h>
#include <math.h>
#include <stdint.h>

// Problem constants
#define PB   8
#define PSL  512
#define PH   768
#define PNS  256
#define PW   32
#define PNH  12
#define PHD  64
#define PFFN 3072
#define PN   2048   // B*NS

// ---------------- scratch (device globals) ----------------------------------
__device__ float  g_pe[PSL * PH];                 // positional encoding table
__device__ __half g_tokpe16[PB * PSL * PH];       // tok + PE, fp16
__device__ float  g_qproj[PH];
__device__ float  g_u[PNH * PH];
__device__ float  g_c[PNH];
__device__ float  g_T[PB * PSL * PNH];
__device__ __half g_v16[PB * PSL * PH];           // V-projection of every token row
__device__ __half g_ctx16[(size_t)PN * PH];
__device__ float  g_att[(size_t)PN * PH];
__device__ float  g_x1[(size_t)PN * PH];
__device__ __half g_x116[(size_t)PN * PH];
__device__ __half g_h16[(size_t)PN * PFFN];
__device__ float  g_z[(size_t)PN * PH];
// fp16 weights
__device__ __half g_wv16[PH * PH];
__device__ __half g_wo16[PH * PH];
__device__ __half g_w116[PFFN * PH];
__device__ __half g_w216[PH * PFFN];

// ---------------- helpers ----------------------------------------------------
__device__ __forceinline__ uint32_t smem_u32(const void* p) {
    uint32_t a;
    asm("{ .reg .u64 t; cvta.to.shared.u64 t, %1; cvt.u32.u64 %0, t; }" : "=r"(a) : "l"(p));
    return a;
}

// ---------------- K0b: q projection -----------------------------------------
__global__ void qproj_kernel(const float* __restrict__ w, const float* __restrict__ b,
                             const float* __restrict__ q0) {
    int gt = blockIdx.x * blockDim.x + threadIdx.x;
    int warp = gt >> 5, lane = gt & 31;
    if (warp >= PH) return;
    const float* wr = w + (size_t)warp * PH;
    float acc = 0.f;
    for (int e = lane; e < PH; e += 32) acc += wr[e] * q0[e];
    #pragma unroll
    for (int o = 16; o; o >>= 1) acc += __shfl_xor_sync(0xffffffffu, acc, o);
    if (!lane) g_qproj[warp] = acc + b[warp];
}

// ---------------- K0c: u_h, c_h ---------------------------------------------
__global__ void uprep_kernel(const float* __restrict__ w, const float* __restrict__ b) {
    int idx = blockIdx.x * blockDim.x + threadIdx.x;
    if (idx < PNH * PH) {
        int h = idx / PH, e = idx % PH;
        float acc = 0.f;
        #pragma unroll 8
        for (int d = 0; d < PHD; d++)
            acc += w[((size_t)(PH + h * PHD + d)) * PH + e] * g_qproj[h * PHD + d];
        g_u[idx] = acc;
    }
    if (idx < PNH) {
        float acc = 0.f;
        #pragma unroll 8
        for (int d = 0; d < PHD; d++)
            acc += g_qproj[idx * PHD + d] * b[PH + idx * PHD + d];
        g_c[idx] = acc;
    }
}

// ---------------- K0e: merged f32->f16 weight conversion + PE table ---------
// blockIdx.y in 0..3: weight conversion; blockIdx.y == 4: PE table rows.
__global__ void f2h4_kernel(const float* s0, __half* d0, int n0,
                            const float* s1, __half* d1, int n1,
                            const float* s2, __half* d2, int n2,
                            const float* s3, __half* d3, int n3) {
    if (blockIdx.y == 4) {
        int pos = blockIdx.x;
        int c4  = threadIdx.x;
        if (pos < PSL && c4 < PH / 4) {
            const float kexp = -9.210340371976184f / (float)PH;
            float e0 = expf((float)(4 * c4) * kexp);
            float e1 = expf((float)(4 * c4 + 2) * kexp);
            float a0 = (float)pos * e0, a1 = (float)pos * e1;
            float4 v;
            v.x = sinf(a0); v.y = cosf(a0);
            v.z = sinf(a1); v.w = cosf(a1);
            ((float4*)g_pe)[pos * (PH / 4) + c4] = v;
        }
        return;
    }
    const float* s; __half* d; int n;
    switch (blockIdx.y) {
        case 0: s = s0; d = d0; n = n0; break;
        case 1: s = s1; d = d1; n = n1; break;
        case 2: s = s2; d = d2; n = n2; break;
        default: s = s3; d = d3; n = n3; break;
    }
    int n4 = n >> 2;
    for (int i = blockIdx.x * blockDim.x + threadIdx.x; i < n4;
         i += gridDim.x * blockDim.x) {
        float4 v = ((const float4*)s)[i];
        half2 h0 = __floats2half2_rn(v.x, v.y);
        half2 h1 = __floats2half2_rn(v.z, v.w);
        uint2 u; u.x = *(uint32_t*)&h0; u.y = *(uint32_t*)&h1;
        ((uint2*)d)[i] = u;
    }
}

// ---------------- K0: fused tok+PE (fp16 out) and T projection ---------------
__global__ __launch_bounds__(128) void tokpe_tproj_kernel(const float* __restrict__ tok) {
    int row  = blockIdx.x * 4 + (threadIdx.x >> 5);   // 0..4095
    int lane = threadIdx.x & 31;
    int pos  = row % PSL;
    const float4* tp = (const float4*)tok + (size_t)row * (PH / 4);
    const float4* pp = (const float4*)g_pe + (size_t)pos * (PH / 4);
    uint2* op = (uint2*)g_tokpe16 + (size_t)row * (PH / 4);

    float4 rr[6];
    #pragma unroll
    for (int j = 0; j < 6; j++) {
        int c4 = lane + 32 * j;
        float4 v = tp[c4];
        float4 p = __ldg(pp + c4);
        v.x += p.x; v.y += p.y; v.z += p.z; v.w += p.w;
        rr[j] = v;
        half2 h0 = __floats2half2_rn(v.x, v.y);
        half2 h1 = __floats2half2_rn(v.z, v.w);
        uint2 u; u.x = *(uint32_t*)&h0; u.y = *(uint32_t*)&h1;
        op[c4] = u;
    }
    #pragma unroll
    for (int h = 0; h < PNH; h++) {
        const float4* up = (const float4*)g_u + h * (PH / 4);
        float acc = 0.f;
        #pragma unroll
        for (int j = 0; j < 6; j++) {
            float4 u4 = __ldg(up + lane + 32 * j);
            acc += rr[j].x * u4.x + rr[j].y * u4.y + rr[j].z * u4.z + rr[j].w * u4.w;
        }
        #pragma unroll
        for (int o = 16; o; o >>= 1) acc += __shfl_xor_sync(0xffffffffu, acc, o);
        if (!lane) g_T[row * PNH + h] = acc;
    }
}

// ---------------- K1: span scores + softmax + ctx pooling from v16 ----------
__global__ __launch_bounds__(192) void span_kernel(const int* __restrict__ ids) {
    __shared__ float s_att[PNH * PW];
    int n = blockIdx.x;
    int b = n >> 8;
    int tid = threadIdx.x;
    int start = ids[2 * n];
    int len   = ids[2 * n + 1] - start;

    for (int i = tid; i < PNH * PW; i += 192) {
        int h = i >> 5, w = i & 31;
        float v = -1e9f;
        if (w < len)
            v = (g_T[(b * PSL + start + w) * PNH + h] + g_c[h]) * 0.125f;
        s_att[h * PW + w] = v;
    }
    __syncthreads();

    int warp = tid >> 5, lane = tid & 31;
    for (int h = warp; h < PNH; h += 6) {
        float v = s_att[h * PW + lane];
        float mx = v;
        #pragma unroll
        for (int o = 16; o; o >>= 1) mx = fmaxf(mx, __shfl_xor_sync(0xffffffffu, mx, o));
        float e = __expf(v - mx);
        float s = e;
        #pragma unroll
        for (int o = 16; o; o >>= 1) s += __shfl_xor_sync(0xffffffffu, s, o);
        s_att[h * PW + lane] = e / s;
    }
    __syncthreads();

    int h = tid >> 4;
    const uint2* vb = (const uint2*)g_v16 + ((size_t)(b * PSL + start)) * (PH / 4) + tid;
    float4 acc = make_float4(0.f, 0.f, 0.f, 0.f);
    #pragma unroll 8
    for (int w = 0; w < PW; w++) {
        uint2 u = vb[(size_t)w * (PH / 4)];
        float2 f0 = __half22float2(*(half2*)&u.x);
        float2 f1 = __half22float2(*(half2*)&u.y);
        float a = s_att[h * PW + w];
        acc.x += a * f0.x; acc.y += a * f0.y;
        acc.z += a * f1.x; acc.w += a * f1.y;
    }
    half2 h0 = __floats2half2_rn(acc.x, acc.y);
    half2 h1 = __floats2half2_rn(acc.z, acc.w);
    uint2 u; u.x = *(uint32_t*)&h0; u.y = *(uint32_t*)&h1;
    ((uint2*)g_ctx16)[(size_t)n * (PH / 4) + tid] = u;
}

// ---------------- fp16 mma.sync GEMM: C = A @ B^T (+bias)(+resid)(relu) -----
// Tile 128(M) x TBN(N) x 64(K halves) per stage, NST-stage cp.async pipeline,
// ONE __syncthreads per stage. 256 threads = 8 warps; ldmatrix fragments.
#define TCM 128
#define KHC 64
#define RSTR 72

template<int TBN, int NST>
__global__ __launch_bounds__(256) void gemm_h_kernel(
    const __half* __restrict__ A, const __half* __restrict__ Bm,
    const float* __restrict__ bias, const float* __restrict__ resid,
    float* __restrict__ Cf, __half* __restrict__ Ch,
    int K, int lda, int ldb, int ldc, int ldr,
    long long sA, long long sB, long long sC, long long sBias, int relu)
{
    constexpr int WNW = TBN / 32;
    constexpr int WMW = 8 / WNW;
    constexpr int WTM = TCM / WMW;
    constexpr int MT  = WTM / 16;
    constexpr int BCH = TBN * 8 / 256;
    constexpr int TPRB = 8 / BCH;
    constexpr int STAGEH = (TCM + TBN) * RSTR;

    extern __shared__ __half smh[];

    int z = blockIdx.z;
    const __half* Ab = A + (size_t)z * sA;
    const __half* Bb = Bm + (size_t)z * sB;
    float* Cfb = Cf ? Cf + (size_t)z * sC : (float*)0;
    __half* Chb = Ch ? Ch + (size_t)z * sC : (__half*)0;
    const float* biasb = bias ? bias + (size_t)z * sBias : (const float*)0;

    int m0 = blockIdx.y * TCM;
    int n0 = blockIdx.x * TBN;
    int tid = threadIdx.x;
    int warp = tid >> 5, lane = tid & 31;
    int grp = lane >> 2, tig = lane & 3;
    int wn = warp % WNW, wm = warp / WNW;

    uint32_t a_lo = ((((lane >> 3) & 1) * 8 + (lane & 7)) * RSTR + (lane >> 4) * 8) * 2;
    uint32_t b_lo = (((lane >> 4) * 8 + (lane & 7)) * RSTR + ((lane >> 3) & 1) * 8) * 2;

    float acc[MT][4][4];
    #pragma unroll
    for (int mt = 0; mt < MT; mt++)
        #pragma unroll
        for (int nt = 0; nt < 4; nt++)
            #pragma unroll
            for (int r = 0; r < 4; r++) acc[mt][nt][r] = 0.f;

    int arow = tid >> 1;
    int acb  = (tid & 1) * 4;
    int brow = tid / TPRB;
    int bcb  = (tid % TPRB) * BCH;

    int nSt = K / KHC;
    uint32_t smb = smem_u32(smh);

    auto issue = [&](int s, int buf) {
        int k0 = s * KHC;
        uint32_t sa = smb + (uint32_t)buf * STAGEH * 2;
        uint32_t sbb = sa + TCM * RSTR * 2;
        const __half* asrc = Ab + (size_t)(m0 + arow) * lda + k0;
        uint32_t adst = sa + (arow * RSTR) * 2;
        #pragma unroll
        for (int j = 0; j < 4; j++) {
            int c = acb + j;
            asm volatile("cp.async.cg.shared.global [%0], [%1], 16;"
                         :: "r"(adst + c * 16), "l"(asrc + c * 8) : "memory");
        }
        const __half* bsrc = Bb + (size_t)(n0 + brow) * ldb + k0;
        uint32_t bdst = sbb + (brow * RSTR) * 2;
        #pragma unroll
        for (int j = 0; j < BCH; j++) {
            int c = bcb + j;
            asm volatile("cp.async.cg.shared.global [%0], [%1], 16;"
                         :: "r"(bdst + c * 16), "l"(bsrc + c * 8) : "memory");
        }
    };

    // prologue: NST-1 stages in flight
    #pragma unroll
    for (int s = 0; s < NST - 1; s++) {
        issue(s, s);
        asm volatile("cp.async.commit_group;" ::: "memory");
    }

    for (int s = 0; s < nSt; s++) {
        asm volatile("cp.async.wait_group %0;" :: "n"(NST - 2) : "memory");
        __syncthreads();
        if (s + NST - 1 < nSt) issue(s + NST - 1, (s + NST - 1) % NST);
        asm volatile("cp.async.commit_group;" ::: "memory");

        uint32_t As_b = smb + (uint32_t)(s % NST) * STAGEH * 2;
        uint32_t Bs_b = As_b + TCM * RSTR * 2;
        #pragma unroll
        for (int kk = 0; kk < 4; kk++) {
            int k = kk * 16;
            uint32_t af[MT][4], bf[4][2];
            #pragma unroll
            for (int mt = 0; mt < MT; mt++) {
                uint32_t ad = As_b + (uint32_t)(((wm * WTM + mt * 16) * RSTR + k) * 2) + a_lo;
                asm volatile("ldmatrix.sync.aligned.m8n8.x4.shared.b16 {%0,%1,%2,%3}, [%4];"
                             : "=r"(af[mt][0]), "=r"(af[mt][1]), "=r"(af[mt][2]), "=r"(af[mt][3])
                             : "r"(ad));
            }
            uint32_t bd0 = Bs_b + (uint32_t)(((wn * 32) * RSTR + k) * 2) + b_lo;
            asm volatile("ldmatrix.sync.aligned.m8n8.x4.shared.b16 {%0,%1,%2,%3}, [%4];"
                         : "=r"(bf[0][0]), "=r"(bf[0][1]), "=r"(bf[1][0]), "=r"(bf[1][1])
                         : "r"(bd0));
            asm volatile("ldmatrix.sync.aligned.m8n8.x4.shared.b16 {%0,%1,%2,%3}, [%4];"
                         : "=r"(bf[2][0]), "=r"(bf[2][1]), "=r"(bf[3][0]), "=r"(bf[3][1])
                         : "r"(bd0 + 16 * RSTR * 2));
            #pragma unroll
            for (int mt = 0; mt < MT; mt++)
                #pragma unroll
                for (int nt = 0; nt < 4; nt++) {
                    asm volatile(
                        "mma.sync.aligned.m16n8k16.row.col.f32.f16.f16.f32 "
                        "{%0,%1,%2,%3}, {%4,%5,%6,%7}, {%8,%9}, {%0,%1,%2,%3};"
                        : "+f"(acc[mt][nt][0]), "+f"(acc[mt][nt][1]),
                          "+f"(acc[mt][nt][2]), "+f"(acc[mt][nt][3])
                        : "r"(af[mt][0]), "r"(af[mt][1]), "r"(af[mt][2]), "r"(af[mt][3]),
                          "r"(bf[nt][0]), "r"(bf[nt][1]));
                }
        }
        // No end-of-stage barrier: buffer s%NST is next written by issue(s+NST),
        // ordered after every warp's stage-s reads by the s+1 top barrier.
    }

    #pragma unroll
    for (int mt = 0; mt < MT; mt++) {
        #pragma unroll
        for (int nt = 0; nt < 4; nt++) {
            int gn = n0 + wn * 32 + nt * 8 + tig * 2;
            float bv0 = biasb ? biasb[gn] : 0.f;
            float bv1 = biasb ? biasb[gn + 1] : 0.f;
            #pragma unroll
            for (int rh = 0; rh < 2; rh++) {
                int gm = m0 + wm * WTM + mt * 16 + grp + rh * 8;
                float v0 = acc[mt][nt][rh * 2 + 0] + bv0;
                float v1 = acc[mt][nt][rh * 2 + 1] + bv1;
                if (resid) {
                    v0 += resid[(size_t)gm * ldr + gn];
                    v1 += resid[(size_t)gm * ldr + gn + 1];
                }
                if (relu) { v0 = fmaxf(v0, 0.f); v1 = fmaxf(v1, 0.f); }
                if (Cfb) {
                    float2 o; o.x = v0; o.y = v1;
                    *(float2*)(Cfb + (size_t)gm * ldc + gn) = o;
                }
                if (Chb)
                    *(half2*)(Chb + (size_t)gm * ldc + gn) = __floats2half2_rn(v0, v1);
            }
        }
    }
}

// ---------------- LayerNorm (optional mask, optional fp16 copy) -------------
__global__ __launch_bounds__(256) void ln_kernel(
    const float* __restrict__ in, const float* __restrict__ gamma,
    const float* __restrict__ beta, const int* __restrict__ ids,
    float* __restrict__ out, __half* __restrict__ out16)
{
    __shared__ float red1[8], red2[8];
    __shared__ float bc1, bc2;
    int row = blockIdx.x, tid = threadIdx.x;
    const float* x = in + (size_t)row * PH;

    float v[3];
    #pragma unroll
    for (int j = 0; j < 3; j++) v[j] = x[tid + j * 256];

    float s = v[0] + v[1] + v[2];
    #pragma unroll
    for (int o = 16; o; o >>= 1) s += __shfl_xor_sync(0xffffffffu, s, o);
    if ((tid & 31) == 0) red1[tid >> 5] = s;
    __syncthreads();
    if (tid < 8) {
        float t = red1[tid];
        #pragma unroll
        for (int o = 4; o; o >>= 1) t += __shfl_xor_sync(0xffu, t, o);
        if (!tid) bc1 = t;
    }
    __syncthreads();
    float mu = bc1 * (1.0f / PH);

    float d0 = v[0] - mu, d1 = v[1] - mu, d2 = v[2] - mu;
    float sq = d0 * d0 + d1 * d1 + d2 * d2;
    #pragma unroll
    for (int o = 16; o; o >>= 1) sq += __shfl_xor_sync(0xffffffffu, sq, o);
    if ((tid & 31) == 0) red2[tid >> 5] = sq;
    __syncthreads();
    if (tid < 8) {
        float t = red2[tid];
        #pragma unroll
        for (int o = 4; o; o >>= 1) t += __shfl_xor_sync(0xffu, t, o);
        if (!tid) bc2 = t;
    }
    __syncthreads();
    float var = bc2 * (1.0f / PH);
    float rs = rsqrtf(var + 1e-5f);

    float mask = 1.0f;
    if (ids) {
        int a = ids[2 * row], b = ids[2 * row + 1];
        if (b - a <= 0) mask = 0.f;
    }
    #pragma unroll
    for (int j = 0; j < 3; j++) {
        int c = tid + j * 256;
        float o = ((v[j] - mu) * rs * gamma[c] + beta[c]) * mask;
        out[(size_t)row * PH + c] = o;
        if (out16) out16[(size_t)row * PH + c] = __float2half_rn(o);
    }
}

// ---------------- launch -----------------------------------------------------
#define SMEM_G128_4 (4 * (TCM + 128) * RSTR * 2)
#define SMEM_G128_3 (3 * (TCM + 128) * RSTR * 2)
#define SMEM_G64_3  (3 * (TCM + 64) * RSTR * 2)

extern "C" void kernel_launch(void* const* d_in, const int* in_sizes, int n_in,
                              void* d_out, int out_size) {
    const float* tok = (const float*)d_in[0];
    const int*   ids = (const int*)d_in[1];
    const float* q0  = (const float*)d_in[2];
    const float* inw = (const float*)d_in[3];
    const float* inb = (const float*)d_in[4];
    const float* ow  = (const float*)d_in[5];
    const float* ob  = (const float*)d_in[6];
    const float* lng = (const float*)d_in[7];
    const float* lnb = (const float*)d_in[8];
    const float* w1  = (const float*)d_in[9];
    const float* b1  = (const float*)d_in[10];
    const float* w2  = (const float*)d_in[11];
    const float* b2  = (const float*)d_in[12];
    float* out = (float*)d_out;

    __half *p_v16, *p_ctx16, *p_x116, *p_h16, *p_tokpe16;
    __half *p_wv16, *p_wo16, *p_w116, *p_w216;
    float *p_att, *p_x1, *p_z;
    cudaGetSymbolAddress((void**)&p_v16,     g_v16);
    cudaGetSymbolAddress((void**)&p_ctx16,   g_ctx16);
    cudaGetSymbolAddress((void**)&p_tokpe16, g_tokpe16);
    cudaGetSymbolAddress((void**)&p_att,     g_att);
    cudaGetSymbolAddress((void**)&p_x1,      g_x1);
    cudaGetSymbolAddress((void**)&p_x116,    g_x116);
    cudaGetSymbolAddress((void**)&p_h16,     g_h16);
    cudaGetSymbolAddress((void**)&p_z,       g_z);
    cudaGetSymbolAddress((void**)&p_wv16,    g_wv16);
    cudaGetSymbolAddress((void**)&p_wo16,    g_wo16);
    cudaGetSymbolAddress((void**)&p_w116,    g_w116);
    cudaGetSymbolAddress((void**)&p_w216,    g_w216);

    cudaFuncSetAttribute((const void*)gemm_h_kernel<128, 4>,
                         cudaFuncAttributeMaxDynamicSharedMemorySize, SMEM_G128_4);
    cudaFuncSetAttribute((const void*)gemm_h_kernel<128, 3>,
                         cudaFuncAttributeMaxDynamicSharedMemorySize, SMEM_G128_3);
    cudaFuncSetAttribute((const void*)gemm_h_kernel<64, 3>,
                         cudaFuncAttributeMaxDynamicSharedMemorySize, SMEM_G64_3);

    // K0: prep (pe folded into f2h4 as blockIdx.y==4)
    qproj_kernel<<<96, 256>>>(inw, inb, q0);
    uprep_kernel<<<36, 256>>>(inw, inb);
    f2h4_kernel<<<dim3(512, 5), 256>>>(
        inw + (size_t)2 * PH * PH, p_wv16, PH * PH,
        ow, p_wo16, PH * PH,
        w1, p_w116, PFFN * PH,
        w2, p_w216, PH * PFFN);
    tokpe_tproj_kernel<<<PB * PSL / 4, 128>>>(tok);

    // K1a: v16 = tokpe16 @ Wv^T + bv  (TBN=128: 192 CTAs, 64x32 warp tiles)
    gemm_h_kernel<128, 3><<<dim3(PH / 128, PB * PSL / TCM, 1), 256, SMEM_G128_3>>>(
        p_tokpe16, p_wv16, inb + 2 * PH, (const float*)0, (float*)0, p_v16,
        PH, PH, PH, PH, 0, 0, 0, 0, 0, 0);

    // K1b: per-span scores/softmax/ctx pooling -> ctx16
    span_kernel<<<PN, 192>>>(ids);

    // K3: att = ctx @ O^T + ob + q0(broadcast)
    gemm_h_kernel<64, 3><<<dim3(PH / 64, PN / TCM, 1), 256, SMEM_G64_3>>>(
        p_ctx16, p_wo16, ob, q0, p_att, (__half*)0,
        PH, PH, PH, PH, 0, 0, 0, 0, 0, 0);

    // K4: x1 = LN(att); also x116
    ln_kernel<<<PN, 256>>>(p_att, lng, lnb, (const int*)0, p_x1, p_x116);

    // K5: h16 = relu(x1 @ W1^T + b1)  (TBN=128, 4 stages: 1 CTA/SM anyway)
    gemm_h_kernel<128, 4><<<dim3(PFFN / 128, PN / TCM, 1), 256, SMEM_G128_4>>>(
        p_x116, p_w116, b1, (const float*)0, (float*)0, p_h16,
        PH, PH, PH, PFFN, 0, 0, 0, 0, 0, 1);

    // K6: z = h @ W2^T + b2 + x1
    gemm_h_kernel<64, 3><<<dim3(PH / 64, PN / TCM, 1), 256, SMEM_G64_3>>>(
        p_h16, p_w216, b2, p_x1, p_z, (__half*)0,
        PFFN, PFFN, PFFN, PH, PH, 0, 0, 0, 0, 0);

    // K7: out = LN(z) masked by length>0
    ln_kernel<<<PN, 256>>>(p_z, lng, lnb, ids, out, (__half*)0);
}

// round 14
// speedup vs baseline: 1.0288x; 1.0288x over previous
#include <cuda_runtime.h>
#include <cuda_fp16.h>
#include <math.h>
#include <stdint.h>

// Problem constants
#define PB   8
#define PSL  512
#define PH   768
#define PNS  256
#define PW   32
#define PNH  12
#define PHD  64
#define PFFN 3072
#define PN   2048   // B*NS

// ---------------- scratch (device globals) ----------------------------------
__device__ float  g_pe[PSL * PH];                 // positional encoding table
__device__ __half g_tokpe16[PB * PSL * PH];       // tok + PE, fp16
__device__ float  g_qproj[PH];
__device__ float  g_u[PNH * PH];
__device__ float  g_c[PNH];
__device__ float  g_T[PB * PSL * PNH];
__device__ __half g_v16[PB * PSL * PH];           // V-projection of every token row
__device__ __half g_ctx16[(size_t)PN * PH];
__device__ float  g_att[(size_t)PN * PH];
__device__ float  g_x1[(size_t)PN * PH];
__device__ __half g_x116[(size_t)PN * PH];
__device__ __half g_h16[(size_t)PN * PFFN];
__device__ float  g_z[(size_t)PN * PH];
// fp16 weights
__device__ __half g_wv16[PH * PH];
__device__ __half g_wo16[PH * PH];
__device__ __half g_w116[PFFN * PH];
__device__ __half g_w216[PH * PFFN];

// ---------------- helpers ----------------------------------------------------
__device__ __forceinline__ uint32_t smem_u32(const void* p) {
    uint32_t a;
    asm("{ .reg .u64 t; cvta.to.shared.u64 t, %1; cvt.u32.u64 %0, t; }" : "=r"(a) : "l"(p));
    return a;
}

// ---------------- K0pe: PE table (512 x 768) ---------------------------------
__global__ __launch_bounds__(192) void pe_kernel() {
    int pos = blockIdx.x;
    int c4  = threadIdx.x;                 // float4 column index, 0..191
    const float kexp = -9.210340371976184f / (float)PH;
    float d0 = expf((float)(4 * c4) * kexp);
    float d1 = expf((float)(4 * c4 + 2) * kexp);
    float a0 = (float)pos * d0, a1 = (float)pos * d1;
    float4 v;
    v.x = sinf(a0); v.y = cosf(a0);
    v.z = sinf(a1); v.w = cosf(a1);
    ((float4*)g_pe)[pos * (PH / 4) + c4] = v;
}

// ---------------- K0b: q projection -----------------------------------------
__global__ void qproj_kernel(const float* __restrict__ w, const float* __restrict__ b,
                             const float* __restrict__ q0) {
    int gt = blockIdx.x * blockDim.x + threadIdx.x;
    int warp = gt >> 5, lane = gt & 31;
    if (warp >= PH) return;
    const float* wr = w + (size_t)warp * PH;
    float acc = 0.f;
    for (int e = lane; e < PH; e += 32) acc += wr[e] * q0[e];
    #pragma unroll
    for (int o = 16; o; o >>= 1) acc += __shfl_xor_sync(0xffffffffu, acc, o);
    if (!lane) g_qproj[warp] = acc + b[warp];
}

// ---------------- K0c: u_h, c_h ---------------------------------------------
__global__ void uprep_kernel(const float* __restrict__ w, const float* __restrict__ b) {
    int idx = blockIdx.x * blockDim.x + threadIdx.x;
    if (idx < PNH * PH) {
        int h = idx / PH, e = idx % PH;
        float acc = 0.f;
        #pragma unroll 8
        for (int d = 0; d < PHD; d++)
            acc += w[((size_t)(PH + h * PHD + d)) * PH + e] * g_qproj[h * PHD + d];
        g_u[idx] = acc;
    }
    if (idx < PNH) {
        float acc = 0.f;
        #pragma unroll 8
        for (int d = 0; d < PHD; d++)
            acc += g_qproj[idx * PHD + d] * b[PH + idx * PHD + d];
        g_c[idx] = acc;
    }
}

// ---------------- K0e: merged f32 -> f16 weight conversion (float4) ---------
__global__ void f2h4_kernel(const float* s0, __half* d0, int n0,
                            const float* s1, __half* d1, int n1,
                            const float* s2, __half* d2, int n2,
                            const float* s3, __half* d3, int n3) {
    const float* s; __half* d; int n;
    switch (blockIdx.y) {
        case 0: s = s0; d = d0; n = n0; break;
        case 1: s = s1; d = d1; n = n1; break;
        case 2: s = s2; d = d2; n = n2; break;
        default: s = s3; d = d3; n = n3; break;
    }
    int n4 = n >> 2;
    for (int i = blockIdx.x * blockDim.x + threadIdx.x; i < n4;
         i += gridDim.x * blockDim.x) {
        float4 v = ((const float4*)s)[i];
        half2 h0 = __floats2half2_rn(v.x, v.y);
        half2 h1 = __floats2half2_rn(v.z, v.w);
        uint2 u; u.x = *(uint32_t*)&h0; u.y = *(uint32_t*)&h1;
        ((uint2*)d)[i] = u;
    }
}

// ---------------- K0: fused tok+PE (fp16 out) and T projection ---------------
// Phase-split: (1) all 12 head partials (independent FMA chains, full MLP),
// (2) 12 butterfly reductions interleaved by level (pipelined shuffles).
__global__ __launch_bounds__(128) void tokpe_tproj_kernel(const float* __restrict__ tok) {
    int row  = blockIdx.x * 4 + (threadIdx.x >> 5);   // 0..4095
    int lane = threadIdx.x & 31;
    int pos  = row % PSL;
    const float4* tp = (const float4*)tok + (size_t)row * (PH / 4);
    const float4* pp = (const float4*)g_pe + (size_t)pos * (PH / 4);
    uint2* op = (uint2*)g_tokpe16 + (size_t)row * (PH / 4);

    float4 rr[6];
    #pragma unroll
    for (int j = 0; j < 6; j++) {
        int c4 = lane + 32 * j;
        float4 v = tp[c4];
        float4 p = __ldg(pp + c4);
        v.x += p.x; v.y += p.y; v.z += p.z; v.w += p.w;
        rr[j] = v;
        half2 h0 = __floats2half2_rn(v.x, v.y);
        half2 h1 = __floats2half2_rn(v.z, v.w);
        uint2 u; u.x = *(uint32_t*)&h0; u.y = *(uint32_t*)&h1;
        op[c4] = u;
    }

    // phase 1: per-lane partials for all 12 heads
    float acc[PNH];
    #pragma unroll
    for (int h = 0; h < PNH; h++) {
        const float4* up = (const float4*)g_u + h * (PH / 4);
        float a = 0.f;
        #pragma unroll
        for (int j = 0; j < 6; j++) {
            float4 u4 = __ldg(up + lane + 32 * j);
            a += rr[j].x * u4.x + rr[j].y * u4.y + rr[j].z * u4.z + rr[j].w * u4.w;
        }
        acc[h] = a;
    }
    // phase 2: 12 butterfly reductions, interleaved by level
    #pragma unroll
    for (int o = 16; o; o >>= 1) {
        #pragma unroll
        for (int h = 0; h < PNH; h++)
            acc[h] += __shfl_xor_sync(0xffffffffu, acc[h], o);
    }
    if (!lane) {
        #pragma unroll
        for (int h = 0; h < PNH; h++)
            g_T[row * PNH + h] = acc[h];
    }
}

// ---------------- K1: span scores + softmax + ctx pooling from v16 ----------
__global__ __launch_bounds__(192) void span_kernel(const int* __restrict__ ids) {
    __shared__ float s_att[PNH * PW];
    int n = blockIdx.x;
    int b = n >> 8;
    int tid = threadIdx.x;
    int start = ids[2 * n];
    int len   = ids[2 * n + 1] - start;

    for (int i = tid; i < PNH * PW; i += 192) {
        int h = i >> 5, w = i & 31;
        float v = -1e9f;
        if (w < len)
            v = (g_T[(b * PSL + start + w) * PNH + h] + g_c[h]) * 0.125f;
        s_att[h * PW + w] = v;
    }
    __syncthreads();

    int warp = tid >> 5, lane = tid & 31;
    for (int h = warp; h < PNH; h += 6) {
        float v = s_att[h * PW + lane];
        float mx = v;
        #pragma unroll
        for (int o = 16; o; o >>= 1) mx = fmaxf(mx, __shfl_xor_sync(0xffffffffu, mx, o));
        float e = __expf(v - mx);
        float s = e;
        #pragma unroll
        for (int o = 16; o; o >>= 1) s += __shfl_xor_sync(0xffffffffu, s, o);
        s_att[h * PW + lane] = e / s;
    }
    __syncthreads();

    int h = tid >> 4;
    const uint2* vb = (const uint2*)g_v16 + ((size_t)(b * PSL + start)) * (PH / 4) + tid;
    float4 acc = make_float4(0.f, 0.f, 0.f, 0.f);
    #pragma unroll 8
    for (int w = 0; w < PW; w++) {
        uint2 u = vb[(size_t)w * (PH / 4)];
        float2 f0 = __half22float2(*(half2*)&u.x);
        float2 f1 = __half22float2(*(half2*)&u.y);
        float a = s_att[h * PW + w];
        acc.x += a * f0.x; acc.y += a * f0.y;
        acc.z += a * f1.x; acc.w += a * f1.y;
    }
    half2 h0 = __floats2half2_rn(acc.x, acc.y);
    half2 h1 = __floats2half2_rn(acc.z, acc.w);
    uint2 u; u.x = *(uint32_t*)&h0; u.y = *(uint32_t*)&h1;
    ((uint2*)g_ctx16)[(size_t)n * (PH / 4) + tid] = u;
}

// ---------------- fp16 mma.sync GEMM: C = A @ B^T (+bias)(+resid)(relu) -----
// Tile 128(M) x TBN(N) x 64(K halves) per stage, 3-stage cp.async pipeline,
// ONE __syncthreads per stage. 256 threads = 8 warps; ldmatrix fragments.
#define TCM 128
#define KHC 64
#define RSTR 72
#define NSTG 3

template<int TBN>
__global__ __launch_bounds__(256) void gemm_h_kernel(
    const __half* __restrict__ A, const __half* __restrict__ Bm,
    const float* __restrict__ bias, const float* __restrict__ resid,
    float* __restrict__ Cf, __half* __restrict__ Ch,
    int K, int lda, int ldb, int ldc, int ldr,
    long long sA, long long sB, long long sC, long long sBias, int relu)
{
    constexpr int WNW = TBN / 32;
    constexpr int WMW = 8 / WNW;
    constexpr int WTM = TCM / WMW;
    constexpr int MT  = WTM / 16;
    constexpr int BCH = TBN * 8 / 256;
    constexpr int TPRB = 8 / BCH;
    constexpr int STAGEH = (TCM + TBN) * RSTR;

    extern __shared__ __half smh[];

    int z = blockIdx.z;
    const __half* Ab = A + (size_t)z * sA;
    const __half* Bb = Bm + (size_t)z * sB;
    float* Cfb = Cf ? Cf + (size_t)z * sC : (float*)0;
    __half* Chb = Ch ? Ch + (size_t)z * sC : (__half*)0;
    const float* biasb = bias ? bias + (size_t)z * sBias : (const float*)0;

    int m0 = blockIdx.y * TCM;
    int n0 = blockIdx.x * TBN;
    int tid = threadIdx.x;
    int warp = tid >> 5, lane = tid & 31;
    int grp = lane >> 2, tig = lane & 3;
    int wn = warp % WNW, wm = warp / WNW;

    uint32_t a_lo = ((((lane >> 3) & 1) * 8 + (lane & 7)) * RSTR + (lane >> 4) * 8) * 2;
    uint32_t b_lo = (((lane >> 4) * 8 + (lane & 7)) * RSTR + ((lane >> 3) & 1) * 8) * 2;

    float acc[MT][4][4];
    #pragma unroll
    for (int mt = 0; mt < MT; mt++)
        #pragma unroll
        for (int nt = 0; nt < 4; nt++)
            #pragma unroll
            for (int r = 0; r < 4; r++) acc[mt][nt][r] = 0.f;

    int arow = tid >> 1;
    int acb  = (tid & 1) * 4;
    int brow = tid / TPRB;
    int bcb  = (tid % TPRB) * BCH;

    int nSt = K / KHC;
    uint32_t smb = smem_u32(smh);

    auto issue = [&](int s, int buf) {
        int k0 = s * KHC;
        uint32_t sa = smb + (uint32_t)buf * STAGEH * 2;
        uint32_t sbb = sa + TCM * RSTR * 2;
        const __half* asrc = Ab + (size_t)(m0 + arow) * lda + k0;
        uint32_t adst = sa + (arow * RSTR) * 2;
        #pragma unroll
        for (int j = 0; j < 4; j++) {
            int c = acb + j;
            asm volatile("cp.async.cg.shared.global [%0], [%1], 16;"
                         :: "r"(adst + c * 16), "l"(asrc + c * 8) : "memory");
        }
        const __half* bsrc = Bb + (size_t)(n0 + brow) * ldb + k0;
        uint32_t bdst = sbb + (brow * RSTR) * 2;
        #pragma unroll
        for (int j = 0; j < BCH; j++) {
            int c = bcb + j;
            asm volatile("cp.async.cg.shared.global [%0], [%1], 16;"
                         :: "r"(bdst + c * 16), "l"(bsrc + c * 8) : "memory");
        }
    };

    issue(0, 0);
    asm volatile("cp.async.commit_group;" ::: "memory");
    issue(1, 1);
    asm volatile("cp.async.commit_group;" ::: "memory");

    for (int s = 0; s < nSt; s++) {
        asm volatile("cp.async.wait_group 1;" ::: "memory");
        __syncthreads();
        if (s + 2 < nSt) issue(s + 2, (s + 2) % NSTG);
        asm volatile("cp.async.commit_group;" ::: "memory");

        uint32_t As_b = smb + (uint32_t)(s % NSTG) * STAGEH * 2;
        uint32_t Bs_b = As_b + TCM * RSTR * 2;
        #pragma unroll
        for (int kk = 0; kk < 4; kk++) {
            int k = kk * 16;
            uint32_t af[MT][4], bf[4][2];
            #pragma unroll
            for (int mt = 0; mt < MT; mt++) {
                uint32_t ad = As_b + (uint32_t)(((wm * WTM + mt * 16) * RSTR + k) * 2) + a_lo;
                asm volatile("ldmatrix.sync.aligned.m8n8.x4.shared.b16 {%0,%1,%2,%3}, [%4];"
                             : "=r"(af[mt][0]), "=r"(af[mt][1]), "=r"(af[mt][2]), "=r"(af[mt][3])
                             : "r"(ad));
            }
            uint32_t bd0 = Bs_b + (uint32_t)(((wn * 32) * RSTR + k) * 2) + b_lo;
            asm volatile("ldmatrix.sync.aligned.m8n8.x4.shared.b16 {%0,%1,%2,%3}, [%4];"
                         : "=r"(bf[0][0]), "=r"(bf[0][1]), "=r"(bf[1][0]), "=r"(bf[1][1])
                         : "r"(bd0));
            asm volatile("ldmatrix.sync.aligned.m8n8.x4.shared.b16 {%0,%1,%2,%3}, [%4];"
                         : "=r"(bf[2][0]), "=r"(bf[2][1]), "=r"(bf[3][0]), "=r"(bf[3][1])
                         : "r"(bd0 + 16 * RSTR * 2));
            #pragma unroll
            for (int mt = 0; mt < MT; mt++)
                #pragma unroll
                for (int nt = 0; nt < 4; nt++) {
                    asm volatile(
                        "mma.sync.aligned.m16n8k16.row.col.f32.f16.f16.f32 "
                        "{%0,%1,%2,%3}, {%4,%5,%6,%7}, {%8,%9}, {%0,%1,%2,%3};"
                        : "+f"(acc[mt][nt][0]), "+f"(acc[mt][nt][1]),
                          "+f"(acc[mt][nt][2]), "+f"(acc[mt][nt][3])
                        : "r"(af[mt][0]), "r"(af[mt][1]), "r"(af[mt][2]), "r"(af[mt][3]),
                          "r"(bf[nt][0]), "r"(bf[nt][1]));
                }
        }
        // No end-of-stage barrier: buffer s%3 is next written by issue(s+3),
        // ordered after every warp's stage-s reads by the s+1 top barrier.
    }

    #pragma unroll
    for (int mt = 0; mt < MT; mt++) {
        #pragma unroll
        for (int nt = 0; nt < 4; nt++) {
            int gn = n0 + wn * 32 + nt * 8 + tig * 2;
            float bv0 = biasb ? biasb[gn] : 0.f;
            float bv1 = biasb ? biasb[gn + 1] : 0.f;
            #pragma unroll
            for (int rh = 0; rh < 2; rh++) {
                int gm = m0 + wm * WTM + mt * 16 + grp + rh * 8;
                float v0 = acc[mt][nt][rh * 2 + 0] + bv0;
                float v1 = acc[mt][nt][rh * 2 + 1] + bv1;
                if (resid) {
                    v0 += resid[(size_t)gm * ldr + gn];
                    v1 += resid[(size_t)gm * ldr + gn + 1];
                }
                if (relu) { v0 = fmaxf(v0, 0.f); v1 = fmaxf(v1, 0.f); }
                if (Cfb) {
                    float2 o; o.x = v0; o.y = v1;
                    *(float2*)(Cfb + (size_t)gm * ldc + gn) = o;
                }
                if (Chb)
                    *(half2*)(Chb + (size_t)gm * ldc + gn) = __floats2half2_rn(v0, v1);
            }
        }
    }
}

// ---------------- LayerNorm (optional mask, optional fp16 copy) -------------
__global__ __launch_bounds__(256) void ln_kernel(
    const float* __restrict__ in, const float* __restrict__ gamma,
    const float* __restrict__ beta, const int* __restrict__ ids,
    float* __restrict__ out, __half* __restrict__ out16)
{
    __shared__ float red1[8], red2[8];
    __shared__ float bc1, bc2;
    int row = blockIdx.x, tid = threadIdx.x;
    const float* x = in + (size_t)row * PH;

    float v[3];
    #pragma unroll
    for (int j = 0; j < 3; j++) v[j] = x[tid + j * 256];

    float s = v[0] + v[1] + v[2];
    #pragma unroll
    for (int o = 16; o; o >>= 1) s += __shfl_xor_sync(0xffffffffu, s, o);
    if ((tid & 31) == 0) red1[tid >> 5] = s;
    __syncthreads();
    if (tid < 8) {
        float t = red1[tid];
        #pragma unroll
        for (int o = 4; o; o >>= 1) t += __shfl_xor_sync(0xffu, t, o);
        if (!tid) bc1 = t;
    }
    __syncthreads();
    float mu = bc1 * (1.0f / PH);

    float d0 = v[0] - mu, d1 = v[1] - mu, d2 = v[2] - mu;
    float sq = d0 * d0 + d1 * d1 + d2 * d2;
    #pragma unroll
    for (int o = 16; o; o >>= 1) sq += __shfl_xor_sync(0xffffffffu, sq, o);
    if ((tid & 31) == 0) red2[tid >> 5] = sq;
    __syncthreads();
    if (tid < 8) {
        float t = red2[tid];
        #pragma unroll
        for (int o = 4; o; o >>= 1) t += __shfl_xor_sync(0xffu, t, o);
        if (!tid) bc2 = t;
    }
    __syncthreads();
    float var = bc2 * (1.0f / PH);
    float rs = rsqrtf(var + 1e-5f);

    float mask = 1.0f;
    if (ids) {
        int a = ids[2 * row], b = ids[2 * row + 1];
        if (b - a <= 0) mask = 0.f;
    }
    #pragma unroll
    for (int j = 0; j < 3; j++) {
        int c = tid + j * 256;
        float o = ((v[j] - mu) * rs * gamma[c] + beta[c]) * mask;
        out[(size_t)row * PH + c] = o;
        if (out16) out16[(size_t)row * PH + c] = __float2half_rn(o);
    }
}

// ---------------- launch -----------------------------------------------------
#define SMEM_G128 (NSTG * (TCM + 128) * RSTR * 2)
#define SMEM_G64  (NSTG * (TCM + 64) * RSTR * 2)

extern "C" void kernel_launch(void* const* d_in, const int* in_sizes, int n_in,
                              void* d_out, int out_size) {
    const float* tok = (const float*)d_in[0];
    const int*   ids = (const int*)d_in[1];
    const float* q0  = (const float*)d_in[2];
    const float* inw = (const float*)d_in[3];
    const float* inb = (const float*)d_in[4];
    const float* ow  = (const float*)d_in[5];
    const float* ob  = (const float*)d_in[6];
    const float* lng = (const float*)d_in[7];
    const float* lnb = (const float*)d_in[8];
    const float* w1  = (const float*)d_in[9];
    const float* b1  = (const float*)d_in[10];
    const float* w2  = (const float*)d_in[11];
    const float* b2  = (const float*)d_in[12];
    float* out = (float*)d_out;

    __half *p_v16, *p_ctx16, *p_x116, *p_h16, *p_tokpe16;
    __half *p_wv16, *p_wo16, *p_w116, *p_w216;
    float *p_att, *p_x1, *p_z;
    cudaGetSymbolAddress((void**)&p_v16,     g_v16);
    cudaGetSymbolAddress((void**)&p_ctx16,   g_ctx16);
    cudaGetSymbolAddress((void**)&p_tokpe16, g_tokpe16);
    cudaGetSymbolAddress((void**)&p_att,     g_att);
    cudaGetSymbolAddress((void**)&p_x1,      g_x1);
    cudaGetSymbolAddress((void**)&p_x116,    g_x116);
    cudaGetSymbolAddress((void**)&p_h16,     g_h16);
    cudaGetSymbolAddress((void**)&p_z,       g_z);
    cudaGetSymbolAddress((void**)&p_wv16,    g_wv16);
    cudaGetSymbolAddress((void**)&p_wo16,    g_wo16);
    cudaGetSymbolAddress((void**)&p_w116,    g_w116);
    cudaGetSymbolAddress((void**)&p_w216,    g_w216);

    cudaFuncSetAttribute(gemm_h_kernel<128>,
                         cudaFuncAttributeMaxDynamicSharedMemorySize, SMEM_G128);
    cudaFuncSetAttribute(gemm_h_kernel<64>,
                         cudaFuncAttributeMaxDynamicSharedMemorySize, SMEM_G64);

    // K0: prep
    pe_kernel<<<PSL, 192>>>();
    qproj_kernel<<<96, 256>>>(inw, inb, q0);
    uprep_kernel<<<36, 256>>>(inw, inb);
    f2h4_kernel<<<dim3(512, 4), 256>>>(
        inw + (size_t)2 * PH * PH, p_wv16, PH * PH,
        ow, p_wo16, PH * PH,
        w1, p_w116, PFFN * PH,
        w2, p_w216, PH * PFFN);
    tokpe_tproj_kernel<<<PB * PSL / 4, 128>>>(tok);

    // K1a: v16 = tokpe16 @ Wv^T + bv  (all 4096 token rows; TBN=64, 384 CTAs)
    gemm_h_kernel<64><<<dim3(PH / 64, PB * PSL / TCM, 1), 256, SMEM_G64>>>(
        p_tokpe16, p_wv16, inb + 2 * PH, (const float*)0, (float*)0, p_v16,
        PH, PH, PH, PH, 0, 0, 0, 0, 0, 0);

    // K1b: per-span scores/softmax/ctx pooling -> ctx16
    span_kernel<<<PN, 192>>>(ids);

    // K3: att = ctx @ O^T + ob + q0(broadcast)
    gemm_h_kernel<64><<<dim3(PH / 64, PN / TCM, 1), 256, SMEM_G64>>>(
        p_ctx16, p_wo16, ob, q0, p_att, (__half*)0,
        PH, PH, PH, PH, 0, 0, 0, 0, 0, 0);

    // K4: x1 = LN(att); also x116
    ln_kernel<<<PN, 256>>>(p_att, lng, lnb, (const int*)0, p_x1, p_x116);

    // K5: h16 = relu(x1 @ W1^T + b1)  (TBN=128)
    gemm_h_kernel<128><<<dim3(PFFN / 128, PN / TCM, 1), 256, SMEM_G128>>>(
        p_x116, p_w116, b1, (const float*)0, (float*)0, p_h16,
        PH, PH, PH, PFFN, 0, 0, 0, 0, 0, 1);

    // K6: z = h @ W2^T + b2 + x1
    gemm_h_kernel<64><<<dim3(PH / 64, PN / TCM, 1), 256, SMEM_G64>>>(
        p_h16, p_w216, b2, p_x1, p_z, (__half*)0,
        PFFN, PFFN, PFFN, PH, PH, 0, 0, 0, 0, 0);

    // K7: out = LN(z) masked by length>0
    ln_kernel<<<PN, 256>>>(p_z, lng, lnb, ids, out, (__half*)0);
}

// round 15
// speedup vs baseline: 1.0871x; 1.0567x over previous
#include <cuda_runtime.h>
#include <cuda_fp16.h>
#include <math.h>
#include <stdint.h>

// Problem constants
#define PB   8
#define PSL  512
#define PH   768
#define PNS  256
#define PW   32
#define PNH  12
#define PHD  64
#define PFFN 3072
#define PN   2048   // B*NS

// ---------------- scratch (device globals) ----------------------------------
__device__ float  g_pe[PSL * PH];                 // positional encoding table
__device__ __half g_tokpe16[PB * PSL * PH];       // tok + PE, fp16
__device__ float  g_qproj[PH];
__device__ float  g_u[PNH * PH];
__device__ float  g_c[PNH];
__device__ float  g_T[PB * PSL * PNH];
__device__ __half g_v16[PB * PSL * PH];           // V-projection of every token row
__device__ __half g_ctx16[(size_t)PN * PH];
__device__ float  g_att[(size_t)PN * PH];
__device__ float  g_x1[(size_t)PN * PH];
__device__ __half g_x116[(size_t)PN * PH];
__device__ __half g_h16[(size_t)PN * PFFN];
__device__ float  g_z[(size_t)PN * PH];
// fp16 weights
__device__ __half g_wv16[PH * PH];
__device__ __half g_wo16[PH * PH];
__device__ __half g_w116[PFFN * PH];
__device__ __half g_w216[PH * PFFN];

// ---------------- helpers ----------------------------------------------------
__device__ __forceinline__ uint32_t smem_u32(const void* p) {
    uint32_t a;
    asm("{ .reg .u64 t; cvta.to.shared.u64 t, %1; cvt.u32.u64 %0, t; }" : "=r"(a) : "l"(p));
    return a;
}

// ---------------- prep1: qproj (y==0) + PE table (y==1) ---------------------
__global__ __launch_bounds__(256) void prep1_kernel(
    const float* __restrict__ w, const float* __restrict__ b,
    const float* __restrict__ q0)
{
    if (blockIdx.y == 1) {
        // PE table: one block per position, 192 active threads (float4 cols)
        int pos = blockIdx.x;
        int c4  = threadIdx.x;
        if (pos < PSL && c4 < PH / 4) {
            const float kexp = -9.210340371976184f / (float)PH;
            float d0 = expf((float)(4 * c4) * kexp);
            float d1 = expf((float)(4 * c4 + 2) * kexp);
            float a0 = (float)pos * d0, a1 = (float)pos * d1;
            float4 v;
            v.x = sinf(a0); v.y = cosf(a0);
            v.z = sinf(a1); v.w = cosf(a1);
            ((float4*)g_pe)[pos * (PH / 4) + c4] = v;
        }
        return;
    }
    // qproj: warp per output row (96 blocks x 8 warps = 768 rows)
    if (blockIdx.x >= 96) return;
    int gt = blockIdx.x * 256 + threadIdx.x;
    int warp = gt >> 5, lane = gt & 31;
    if (warp >= PH) return;
    const float* wr = w + (size_t)warp * PH;
    float acc = 0.f;
    for (int e = lane; e < PH; e += 32) acc += wr[e] * q0[e];
    #pragma unroll
    for (int o = 16; o; o >>= 1) acc += __shfl_xor_sync(0xffffffffu, acc, o);
    if (!lane) g_qproj[warp] = acc + b[warp];
}

// ---------------- prep2: f2h weight conversion (y 0..3) + uprep (y==4) ------
__global__ __launch_bounds__(256) void prep2_kernel(
    const float* s0, __half* d0, int n0,
    const float* s1, __half* d1, int n1,
    const float* s2, __half* d2, int n2,
    const float* s3, __half* d3, int n3,
    const float* __restrict__ wfull, const float* __restrict__ bfull)
{
    if (blockIdx.y == 4) {
        // uprep: u_h, c_h (needs g_qproj from prep1)
        if (blockIdx.x >= 36) return;
        int idx = blockIdx.x * 256 + threadIdx.x;
        if (idx < PNH * PH) {
            int h = idx / PH, e = idx % PH;
            float acc = 0.f;
            #pragma unroll 8
            for (int d = 0; d < PHD; d++)
                acc += wfull[((size_t)(PH + h * PHD + d)) * PH + e] * g_qproj[h * PHD + d];
            g_u[idx] = acc;
        }
        if (idx < PNH) {
            float acc = 0.f;
            #pragma unroll 8
            for (int d = 0; d < PHD; d++)
                acc += g_qproj[idx * PHD + d] * bfull[PH + idx * PHD + d];
            g_c[idx] = acc;
        }
        return;
    }
    const float* s; __half* d; int n;
    switch (blockIdx.y) {
        case 0: s = s0; d = d0; n = n0; break;
        case 1: s = s1; d = d1; n = n1; break;
        case 2: s = s2; d = d2; n = n2; break;
        default: s = s3; d = d3; n = n3; break;
    }
    int n4 = n >> 2;
    for (int i = blockIdx.x * blockDim.x + threadIdx.x; i < n4;
         i += gridDim.x * blockDim.x) {
        float4 v = ((const float4*)s)[i];
        half2 h0 = __floats2half2_rn(v.x, v.y);
        half2 h1 = __floats2half2_rn(v.z, v.w);
        uint2 u; u.x = *(uint32_t*)&h0; u.y = *(uint32_t*)&h1;
        ((uint2*)d)[i] = u;
    }
}

// ---------------- K0: fused tok+PE (fp16 out) and T projection ---------------
__global__ __launch_bounds__(128) void tokpe_tproj_kernel(const float* __restrict__ tok) {
    int row  = blockIdx.x * 4 + (threadIdx.x >> 5);   // 0..4095
    int lane = threadIdx.x & 31;
    int pos  = row % PSL;
    const float4* tp = (const float4*)tok + (size_t)row * (PH / 4);
    const float4* pp = (const float4*)g_pe + (size_t)pos * (PH / 4);
    uint2* op = (uint2*)g_tokpe16 + (size_t)row * (PH / 4);

    float4 rr[6];
    #pragma unroll
    for (int j = 0; j < 6; j++) {
        int c4 = lane + 32 * j;
        float4 v = tp[c4];
        float4 p = __ldg(pp + c4);
        v.x += p.x; v.y += p.y; v.z += p.z; v.w += p.w;
        rr[j] = v;
        half2 h0 = __floats2half2_rn(v.x, v.y);
        half2 h1 = __floats2half2_rn(v.z, v.w);
        uint2 u; u.x = *(uint32_t*)&h0; u.y = *(uint32_t*)&h1;
        op[c4] = u;
    }
    #pragma unroll
    for (int h = 0; h < PNH; h++) {
        const float4* up = (const float4*)g_u + h * (PH / 4);
        float acc = 0.f;
        #pragma unroll
        for (int j = 0; j < 6; j++) {
            float4 u4 = __ldg(up + lane + 32 * j);
            acc += rr[j].x * u4.x + rr[j].y * u4.y + rr[j].z * u4.z + rr[j].w * u4.w;
        }
        #pragma unroll
        for (int o = 16; o; o >>= 1) acc += __shfl_xor_sync(0xffffffffu, acc, o);
        if (!lane) g_T[row * PNH + h] = acc;
    }
}

// ---------------- K1: span scores + softmax + ctx pooling from v16 ----------
__global__ __launch_bounds__(192) void span_kernel(const int* __restrict__ ids) {
    __shared__ float s_att[PNH * PW];
    int n = blockIdx.x;
    int b = n >> 8;
    int tid = threadIdx.x;
    int start = ids[2 * n];
    int len   = ids[2 * n + 1] - start;

    for (int i = tid; i < PNH * PW; i += 192) {
        int h = i >> 5, w = i & 31;
        float v = -1e9f;
        if (w < len)
            v = (g_T[(b * PSL + start + w) * PNH + h] + g_c[h]) * 0.125f;
        s_att[h * PW + w] = v;
    }
    __syncthreads();

    int warp = tid >> 5, lane = tid & 31;
    for (int h = warp; h < PNH; h += 6) {
        float v = s_att[h * PW + lane];
        float mx = v;
        #pragma unroll
        for (int o = 16; o; o >>= 1) mx = fmaxf(mx, __shfl_xor_sync(0xffffffffu, mx, o));
        float e = __expf(v - mx);
        float s = e;
        #pragma unroll
        for (int o = 16; o; o >>= 1) s += __shfl_xor_sync(0xffffffffu, s, o);
        s_att[h * PW + lane] = e / s;
    }
    __syncthreads();

    int h = tid >> 4;
    const uint2* vb = (const uint2*)g_v16 + ((size_t)(b * PSL + start)) * (PH / 4) + tid;
    float4 acc = make_float4(0.f, 0.f, 0.f, 0.f);
    #pragma unroll 8
    for (int w = 0; w < PW; w++) {
        uint2 u = vb[(size_t)w * (PH / 4)];
        float2 f0 = __half22float2(*(half2*)&u.x);
        float2 f1 = __half22float2(*(half2*)&u.y);
        float a = s_att[h * PW + w];
        acc.x += a * f0.x; acc.y += a * f0.y;
        acc.z += a * f1.x; acc.w += a * f1.y;
    }
    half2 h0 = __floats2half2_rn(acc.x, acc.y);
    half2 h1 = __floats2half2_rn(acc.z, acc.w);
    uint2 u; u.x = *(uint32_t*)&h0; u.y = *(uint32_t*)&h1;
    ((uint2*)g_ctx16)[(size_t)n * (PH / 4) + tid] = u;
}

// ---------------- fp16 mma.sync GEMM: C = A @ B^T (+bias)(+resid)(relu) -----
// Tile 128(M) x TBN(N) x 64(K halves) per stage, 3-stage cp.async pipeline,
// ONE __syncthreads per stage. 256 threads = 8 warps; ldmatrix fragments.
#define TCM 128
#define KHC 64
#define RSTR 72
#define NSTG 3

template<int TBN>
__global__ __launch_bounds__(256) void gemm_h_kernel(
    const __half* __restrict__ A, const __half* __restrict__ Bm,
    const float* __restrict__ bias, const float* __restrict__ resid,
    float* __restrict__ Cf, __half* __restrict__ Ch,
    int K, int lda, int ldb, int ldc, int ldr,
    long long sA, long long sB, long long sC, long long sBias, int relu)
{
    constexpr int WNW = TBN / 32;
    constexpr int WMW = 8 / WNW;
    constexpr int WTM = TCM / WMW;
    constexpr int MT  = WTM / 16;
    constexpr int BCH = TBN * 8 / 256;
    constexpr int TPRB = 8 / BCH;
    constexpr int STAGEH = (TCM + TBN) * RSTR;

    extern __shared__ __half smh[];

    int z = blockIdx.z;
    const __half* Ab = A + (size_t)z * sA;
    const __half* Bb = Bm + (size_t)z * sB;
    float* Cfb = Cf ? Cf + (size_t)z * sC : (float*)0;
    __half* Chb = Ch ? Ch + (size_t)z * sC : (__half*)0;
    const float* biasb = bias ? bias + (size_t)z * sBias : (const float*)0;

    int m0 = blockIdx.y * TCM;
    int n0 = blockIdx.x * TBN;
    int tid = threadIdx.x;
    int warp = tid >> 5, lane = tid & 31;
    int grp = lane >> 2, tig = lane & 3;
    int wn = warp % WNW, wm = warp / WNW;

    uint32_t a_lo = ((((lane >> 3) & 1) * 8 + (lane & 7)) * RSTR + (lane >> 4) * 8) * 2;
    uint32_t b_lo = (((lane >> 4) * 8 + (lane & 7)) * RSTR + ((lane >> 3) & 1) * 8) * 2;

    float acc[MT][4][4];
    #pragma unroll
    for (int mt = 0; mt < MT; mt++)
        #pragma unroll
        for (int nt = 0; nt < 4; nt++)
            #pragma unroll
            for (int r = 0; r < 4; r++) acc[mt][nt][r] = 0.f;

    int arow = tid >> 1;
    int acb  = (tid & 1) * 4;
    int brow = tid / TPRB;
    int bcb  = (tid % TPRB) * BCH;

    int nSt = K / KHC;
    uint32_t smb = smem_u32(smh);

    auto issue = [&](int s, int buf) {
        int k0 = s * KHC;
        uint32_t sa = smb + (uint32_t)buf * STAGEH * 2;
        uint32_t sbb = sa + TCM * RSTR * 2;
        const __half* asrc = Ab + (size_t)(m0 + arow) * lda + k0;
        uint32_t adst = sa + (arow * RSTR) * 2;
        #pragma unroll
        for (int j = 0; j < 4; j++) {
            int c = acb + j;
            asm volatile("cp.async.cg.shared.global [%0], [%1], 16;"
                         :: "r"(adst + c * 16), "l"(asrc + c * 8) : "memory");
        }
        const __half* bsrc = Bb + (size_t)(n0 + brow) * ldb + k0;
        uint32_t bdst = sbb + (brow * RSTR) * 2;
        #pragma unroll
        for (int j = 0; j < BCH; j++) {
            int c = bcb + j;
            asm volatile("cp.async.cg.shared.global [%0], [%1], 16;"
                         :: "r"(bdst + c * 16), "l"(bsrc + c * 8) : "memory");
        }
    };

    issue(0, 0);
    asm volatile("cp.async.commit_group;" ::: "memory");
    issue(1, 1);
    asm volatile("cp.async.commit_group;" ::: "memory");

    for (int s = 0; s < nSt; s++) {
        asm volatile("cp.async.wait_group 1;" ::: "memory");
        __syncthreads();
        if (s + 2 < nSt) issue(s + 2, (s + 2) % NSTG);
        asm volatile("cp.async.commit_group;" ::: "memory");

        uint32_t As_b = smb + (uint32_t)(s % NSTG) * STAGEH * 2;
        uint32_t Bs_b = As_b + TCM * RSTR * 2;
        #pragma unroll
        for (int kk = 0; kk < 4; kk++) {
            int k = kk * 16;
            uint32_t af[MT][4], bf[4][2];
            #pragma unroll
            for (int mt = 0; mt < MT; mt++) {
                uint32_t ad = As_b + (uint32_t)(((wm * WTM + mt * 16) * RSTR + k) * 2) + a_lo;
                asm volatile("ldmatrix.sync.aligned.m8n8.x4.shared.b16 {%0,%1,%2,%3}, [%4];"
                             : "=r"(af[mt][0]), "=r"(af[mt][1]), "=r"(af[mt][2]), "=r"(af[mt][3])
                             : "r"(ad));
            }
            uint32_t bd0 = Bs_b + (uint32_t)(((wn * 32) * RSTR + k) * 2) + b_lo;
            asm volatile("ldmatrix.sync.aligned.m8n8.x4.shared.b16 {%0,%1,%2,%3}, [%4];"
                         : "=r"(bf[0][0]), "=r"(bf[0][1]), "=r"(bf[1][0]), "=r"(bf[1][1])
                         : "r"(bd0));
            asm volatile("ldmatrix.sync.aligned.m8n8.x4.shared.b16 {%0,%1,%2,%3}, [%4];"
                         : "=r"(bf[2][0]), "=r"(bf[2][1]), "=r"(bf[3][0]), "=r"(bf[3][1])
                         : "r"(bd0 + 16 * RSTR * 2));
            #pragma unroll
            for (int mt = 0; mt < MT; mt++)
                #pragma unroll
                for (int nt = 0; nt < 4; nt++) {
                    asm volatile(
                        "mma.sync.aligned.m16n8k16.row.col.f32.f16.f16.f32 "
                        "{%0,%1,%2,%3}, {%4,%5,%6,%7}, {%8,%9}, {%0,%1,%2,%3};"
                        : "+f"(acc[mt][nt][0]), "+f"(acc[mt][nt][1]),
                          "+f"(acc[mt][nt][2]), "+f"(acc[mt][nt][3])
                        : "r"(af[mt][0]), "r"(af[mt][1]), "r"(af[mt][2]), "r"(af[mt][3]),
                          "r"(bf[nt][0]), "r"(bf[nt][1]));
                }
        }
        // No end-of-stage barrier: buffer s%3 is next written by issue(s+3),
        // ordered after every warp's stage-s reads by the s+1 top barrier.
    }

    #pragma unroll
    for (int mt = 0; mt < MT; mt++) {
        #pragma unroll
        for (int nt = 0; nt < 4; nt++) {
            int gn = n0 + wn * 32 + nt * 8 + tig * 2;
            float bv0 = biasb ? biasb[gn] : 0.f;
            float bv1 = biasb ? biasb[gn + 1] : 0.f;
            #pragma unroll
            for (int rh = 0; rh < 2; rh++) {
                int gm = m0 + wm * WTM + mt * 16 + grp + rh * 8;
                float v0 = acc[mt][nt][rh * 2 + 0] + bv0;
                float v1 = acc[mt][nt][rh * 2 + 1] + bv1;
                if (resid) {
                    v0 += resid[(size_t)gm * ldr + gn];
                    v1 += resid[(size_t)gm * ldr + gn + 1];
                }
                if (relu) { v0 = fmaxf(v0, 0.f); v1 = fmaxf(v1, 0.f); }
                if (Cfb) {
                    float2 o; o.x = v0; o.y = v1;
                    *(float2*)(Cfb + (size_t)gm * ldc + gn) = o;
                }
                if (Chb)
                    *(half2*)(Chb + (size_t)gm * ldc + gn) = __floats2half2_rn(v0, v1);
            }
        }
    }
}

// ---------------- LayerNorm (optional mask, optional fp16 copy) -------------
__global__ __launch_bounds__(256) void ln_kernel(
    const float* __restrict__ in, const float* __restrict__ gamma,
    const float* __restrict__ beta, const int* __restrict__ ids,
    float* __restrict__ out, __half* __restrict__ out16)
{
    __shared__ float red1[8], red2[8];
    __shared__ float bc1, bc2;
    int row = blockIdx.x, tid = threadIdx.x;
    const float* x = in + (size_t)row * PH;

    float v[3];
    #pragma unroll
    for (int j = 0; j < 3; j++) v[j] = x[tid + j * 256];

    float s = v[0] + v[1] + v[2];
    #pragma unroll
    for (int o = 16; o; o >>= 1) s += __shfl_xor_sync(0xffffffffu, s, o);
    if ((tid & 31) == 0) red1[tid >> 5] = s;
    __syncthreads();
    if (tid < 8) {
        float t = red1[tid];
        #pragma unroll
        for (int o = 4; o; o >>= 1) t += __shfl_xor_sync(0xffu, t, o);
        if (!tid) bc1 = t;
    }
    __syncthreads();
    float mu = bc1 * (1.0f / PH);

    float d0 = v[0] - mu, d1 = v[1] - mu, d2 = v[2] - mu;
    float sq = d0 * d0 + d1 * d1 + d2 * d2;
    #pragma unroll
    for (int o = 16; o; o >>= 1) sq += __shfl_xor_sync(0xffffffffu, sq, o);
    if ((tid & 31) == 0) red2[tid >> 5] = sq;
    __syncthreads();
    if (tid < 8) {
        float t = red2[tid];
        #pragma unroll
        for (int o = 4; o; o >>= 1) t += __shfl_xor_sync(0xffu, t, o);
        if (!tid) bc2 = t;
    }
    __syncthreads();
    float var = bc2 * (1.0f / PH);
    float rs = rsqrtf(var + 1e-5f);

    float mask = 1.0f;
    if (ids) {
        int a = ids[2 * row], b = ids[2 * row + 1];
        if (b - a <= 0) mask = 0.f;
    }
    #pragma unroll
    for (int j = 0; j < 3; j++) {
        int c = tid + j * 256;
        float o = ((v[j] - mu) * rs * gamma[c] + beta[c]) * mask;
        out[(size_t)row * PH + c] = o;
        if (out16) out16[(size_t)row * PH + c] = __float2half_rn(o);
    }
}

// ---------------- launch -----------------------------------------------------
#define SMEM_G128 (NSTG * (TCM + 128) * RSTR * 2)
#define SMEM_G64  (NSTG * (TCM + 64) * RSTR * 2)

extern "C" void kernel_launch(void* const* d_in, const int* in_sizes, int n_in,
                              void* d_out, int out_size) {
    const float* tok = (const float*)d_in[0];
    const int*   ids = (const int*)d_in[1];
    const float* q0  = (const float*)d_in[2];
    const float* inw = (const float*)d_in[3];
    const float* inb = (const float*)d_in[4];
    const float* ow  = (const float*)d_in[5];
    const float* ob  = (const float*)d_in[6];
    const float* lng = (const float*)d_in[7];
    const float* lnb = (const float*)d_in[8];
    const float* w1  = (const float*)d_in[9];
    const float* b1  = (const float*)d_in[10];
    const float* w2  = (const float*)d_in[11];
    const float* b2  = (const float*)d_in[12];
    float* out = (float*)d_out;

    __half *p_v16, *p_ctx16, *p_x116, *p_h16, *p_tokpe16;
    __half *p_wv16, *p_wo16, *p_w116, *p_w216;
    float *p_att, *p_x1, *p_z;
    cudaGetSymbolAddress((void**)&p_v16,     g_v16);
    cudaGetSymbolAddress((void**)&p_ctx16,   g_ctx16);
    cudaGetSymbolAddress((void**)&p_tokpe16, g_tokpe16);
    cudaGetSymbolAddress((void**)&p_att,     g_att);
    cudaGetSymbolAddress((void**)&p_x1,      g_x1);
    cudaGetSymbolAddress((void**)&p_x116,    g_x116);
    cudaGetSymbolAddress((void**)&p_h16,     g_h16);
    cudaGetSymbolAddress((void**)&p_z,       g_z);
    cudaGetSymbolAddress((void**)&p_wv16,    g_wv16);
    cudaGetSymbolAddress((void**)&p_wo16,    g_wo16);
    cudaGetSymbolAddress((void**)&p_w116,    g_w116);
    cudaGetSymbolAddress((void**)&p_w216,    g_w216);

    cudaFuncSetAttribute(gemm_h_kernel<128>,
                         cudaFuncAttributeMaxDynamicSharedMemorySize, SMEM_G128);
    cudaFuncSetAttribute(gemm_h_kernel<64>,
                         cudaFuncAttributeMaxDynamicSharedMemorySize, SMEM_G64);

    // K0: prep (3 launches)
    prep1_kernel<<<dim3(512, 2), 256>>>(inw, inb, q0);
    prep2_kernel<<<dim3(512, 5), 256>>>(
        inw + (size_t)2 * PH * PH, p_wv16, PH * PH,
        ow, p_wo16, PH * PH,
        w1, p_w116, PFFN * PH,
        w2, p_w216, PH * PFFN,
        inw, inb);
    tokpe_tproj_kernel<<<PB * PSL / 4, 128>>>(tok);

    // K1a: v16 = tokpe16 @ Wv^T + bv  (all 4096 token rows; TBN=64, 384 CTAs)
    gemm_h_kernel<64><<<dim3(PH / 64, PB * PSL / TCM, 1), 256, SMEM_G64>>>(
        p_tokpe16, p_wv16, inb + 2 * PH, (const float*)0, (float*)0, p_v16,
        PH, PH, PH, PH, 0, 0, 0, 0, 0, 0);

    // K1b: per-span scores/softmax/ctx pooling -> ctx16
    span_kernel<<<PN, 192>>>(ids);

    // K3: att = ctx @ O^T + ob + q0(broadcast)
    gemm_h_kernel<64><<<dim3(PH / 64, PN / TCM, 1), 256, SMEM_G64>>>(
        p_ctx16, p_wo16, ob, q0, p_att, (__half*)0,
        PH, PH, PH, PH, 0, 0, 0, 0, 0, 0);

    // K4: x1 = LN(att); also x116
    ln_kernel<<<PN, 256>>>(p_att, lng, lnb, (const int*)0, p_x1, p_x116);

    // K5: h16 = relu(x1 @ W1^T + b1)  (TBN=128)
    gemm_h_kernel<128><<<dim3(PFFN / 128, PN / TCM, 1), 256, SMEM_G128>>>(
        p_x116, p_w116, b1, (const float*)0, (float*)0, p_h16,
        PH, PH, PH, PFFN, 0, 0, 0, 0, 0, 1);

    // K6: z = h @ W2^T + b2 + x1
    gemm_h_kernel<64><<<dim3(PH / 64, PN / TCM, 1), 256, SMEM_G64>>>(
        p_h16, p_w216, b2, p_x1, p_z, (__half*)0,
        PFFN, PFFN, PFFN, PH, PH, 0, 0, 0, 0, 0);

    // K7: out = LN(z) masked by length>0
    ln_kernel<<<PN, 256>>>(p_z, lng, lnb, ids, out, (__half*)0);
}